// round 3
// baseline (speedup 1.0000x reference)
#include <cuda_runtime.h>
#include <cuda_bf16.h>

// Shapes (fixed by the problem)
#define DIMN 1024
#define HH 8
#define DD 64
#define LL 256
#define HD 512           // H*D
#define OUT_Y (LL*DIMN)  // 262144

// ---------------- scratch (device globals; no allocation allowed) ----------
__device__ float  g_t1[LL*DIMN];
__device__ float  g_t2[LL*DIMN*2];
__device__ float2 g_xc[LL*HD];
__device__ float2 g_a[LL*HD];
__device__ float2 g_vinv[HH*DD*DD];
__device__ float2 g_w[(LL+1)*HD];
__device__ float2 g_heig[LL*HD];
__device__ float  g_hr[LL*DIMN];
__device__ float  g_y1[LL*DIMN];

__device__ __forceinline__ float2 cmulf(float2 a, float2 b) {
    return make_float2(a.x*b.x - a.y*b.y, a.x*b.y + a.y*b.x);
}

// ---------------- GEMM: C[M,N] = act(A[M,K] @ W[K,N] + bias) ----------------
#define BM 64
#define BN 64
#define BK 16
__global__ __launch_bounds__(256) void gemm_kernel(
    const float* __restrict__ A, const float* __restrict__ W,
    const float* __restrict__ bias, float* __restrict__ C,
    int M, int N, int K, int act)
{
    __shared__ float As[BK][BM];
    __shared__ float Bs[BK][BN+4];
    int tid = threadIdx.x;
    int tx = tid % 16, ty = tid / 16;
    int row0 = blockIdx.y*BM + ty*4;
    int col0 = blockIdx.x*BN + tx*4;

    float acc[4][4] = {};

    int arow = tid >> 2;          // 0..63
    int acol = (tid & 3) << 2;    // 0,4,8,12
    int wrow = tid >> 4;          // 0..15
    int wcol = (tid & 15) << 2;   // 0..60

    const float* Aptr = A + (blockIdx.y*BM + arow)*K + acol;
    const float* Wptr = W + wrow*N + blockIdx.x*BN + wcol;

    for (int k0 = 0; k0 < K; k0 += BK) {
        float4 av = *(const float4*)(Aptr + k0);
        As[acol+0][arow] = av.x;
        As[acol+1][arow] = av.y;
        As[acol+2][arow] = av.z;
        As[acol+3][arow] = av.w;
        float4 wv = *(const float4*)(Wptr + (size_t)k0*N);
        *(float4*)&Bs[wrow][wcol] = wv;
        __syncthreads();
#pragma unroll
        for (int k = 0; k < BK; k++) {
            float ra[4], rb[4];
#pragma unroll
            for (int i = 0; i < 4; i++) ra[i] = As[k][ty*4+i];
#pragma unroll
            for (int j = 0; j < 4; j++) rb[j] = Bs[k][tx*4+j];
#pragma unroll
            for (int i = 0; i < 4; i++)
#pragma unroll
                for (int j = 0; j < 4; j++)
                    acc[i][j] = fmaf(ra[i], rb[j], acc[i][j]);
        }
        __syncthreads();
    }
#pragma unroll
    for (int i = 0; i < 4; i++) {
#pragma unroll
        for (int j = 0; j < 4; j++) {
            int c = col0 + j;
            float v = acc[i][j] + bias[c];
            if (act) v = v / (1.0f + expf(-v));   // silu
            C[(size_t)(row0+i)*N + c] = v;
        }
    }
}

// ---------------- prep: split t2 into xc and normalized a ------------------
__global__ void prep_kernel(const float* __restrict__ t2,
                            float2* __restrict__ xc, float2* __restrict__ a)
{
    int e = blockIdx.x*blockDim.x + threadIdx.x;
    if (e >= LL*HD) return;
    int l = e >> 9, hd = e & 511;
    const float* p = t2 + (size_t)l*2048 + hd*4;
    float xr = p[0], xi = p[1], ar = p[2], ai = p[3];
    xc[e] = make_float2(xr, xi);
    float m2 = ar*ar + ai*ai;
    float f = (m2/(1.0f+m2)) * rsqrtf(m2);   // sigmoid(log m2) * rsqrt(m2)
    a[e] = make_float2(ar*f, ai*f);
}

// ---------------- complex 64x64 inverse (Gauss-Jordan, partial pivot) ------
__global__ void inv_kernel(const float* __restrict__ vr, const float* __restrict__ vi,
                           float2* __restrict__ vinv)
{
    extern __shared__ float2 sh[];
    float2* Am = sh;          // 64*64
    float2* Im = sh + 4096;   // 64*64
    __shared__ float2 fac[64];
    __shared__ int piv;
    int h = blockIdx.x;
    int t = threadIdx.x;   // 256 threads

    for (int i = t; i < 4096; i += 256) {
        int n = i >> 6, o = i & 63;
        Am[i] = make_float2(vr[h*4096 + i], vi[h*4096 + i]);
        Im[i] = make_float2(n == o ? 1.0f : 0.0f, 0.0f);
    }
    __syncthreads();

    for (int k = 0; k < 64; k++) {
        if (t == 0) {
            float best = -1.0f; int bp = k;
            for (int r = k; r < 64; r++) {
                float2 v = Am[r*64+k];
                float m = v.x*v.x + v.y*v.y;
                if (m > best) { best = m; bp = r; }
            }
            piv = bp;
        }
        __syncthreads();
        int p = piv;
        if (p != k) {
            if (t < 128) {
                float2* Mm = (t < 64) ? Am : Im;
                int c = t & 63;
                float2 tmp = Mm[k*64+c];
                Mm[k*64+c] = Mm[p*64+c];
                Mm[p*64+c] = tmp;
            }
            __syncthreads();
        }
        // scale row k by 1/pivot
        float2 pv = Am[k*64+k];
        float im2 = 1.0f/(pv.x*pv.x + pv.y*pv.y);
        float2 pinv = make_float2(pv.x*im2, -pv.y*im2);
        if (t < 128) {
            float2* Mm = (t < 64) ? Am : Im;
            int c = t & 63;
            Mm[k*64+c] = cmulf(Mm[k*64+c], pinv);
        }
        __syncthreads();
        if (t < 64) fac[t] = Am[t*64+k];
        __syncthreads();
        // eliminate: thread -> (matrix, col, row-parity)
        {
            int c = t & 63;
            float2* Mm = ((t >> 6) & 1) ? Im : Am;
            int rstart = t >> 7;                 // 0 or 1
            float2 pk = Mm[k*64+c];
            for (int r = rstart; r < 64; r += 2) {
                if (r == k) continue;
                float2 f = fac[r];
                float2 v = Mm[r*64+c];
                v.x -= f.x*pk.x - f.y*pk.y;
                v.y -= f.x*pk.y + f.y*pk.x;
                Mm[r*64+c] = v;
            }
        }
        __syncthreads();
    }
    for (int i = t; i < 4096; i += 256) vinv[h*4096 + i] = Im[i];
}

// ---------------- w[li] = Vinv[h] @ x_roll-extended ------------------------
// li = 0 -> hidden; li = 1..256 -> xc[li-1]
__global__ void matvec_vinv_kernel(const float2* __restrict__ vinv,
                                   const float2* __restrict__ xc,
                                   const float* __restrict__ hreal,
                                   const float* __restrict__ himag,
                                   float2* __restrict__ w)
{
    int li = blockIdx.x;   // 0..256
    int h  = blockIdx.y;   // 0..7
    int n  = threadIdx.x;  // 0..63
    __shared__ float2 vec[64];
    if (li == 0) vec[n] = make_float2(hreal[h*64+n], himag[h*64+n]);
    else         vec[n] = xc[(li-1)*HD + h*64 + n];
    __syncthreads();
    const float2* Vh = vinv + h*4096 + n*64;
    float2 acc = make_float2(0.0f, 0.0f);
#pragma unroll 8
    for (int o = 0; o < 64; o++) {
        float2 m = Vh[o], v = vec[o];
        acc.x += m.x*v.x - m.y*v.y;
        acc.y += m.x*v.y + m.y*v.x;
    }
    w[li*HD + h*64 + n] = acc;
}

// ---------------- sequential diagonal recurrence ---------------------------
// s[m] = a[m]*(s[m-1] + w[m]);  heig[m] = s[m] + w[m+1]
__global__ void scan_kernel(const float2* __restrict__ a,
                            const float2* __restrict__ w,
                            float2* __restrict__ heig)
{
    int hd = threadIdx.x;  // 512 threads
    float2 s = make_float2(0.0f, 0.0f);
    for (int m = 0; m < LL; m++) {
        float2 wm = w[m*HD + hd];
        float2 am = a[m*HD + hd];
        float2 tv = make_float2(s.x + wm.x, s.y + wm.y);
        s = cmulf(am, tv);
        float2 wn = w[(m+1)*HD + hd];
        heig[m*HD + hd] = make_float2(s.x + wn.x, s.y + wn.y);
    }
}

// ---------------- out_h[l] = V[h] @ heig[l]; pack hr; emit hidden_next -----
// hidden_next layout depends on out_size:
//   out_size >= OUT_Y+1024 : interleaved (re,im) float pairs at OUT_Y
//   out_size >= OUT_Y+512  : real part only at OUT_Y (harness astype(float32))
__global__ void matvec_v_kernel(const float* __restrict__ vr,
                                const float* __restrict__ vi,
                                const float2* __restrict__ heig,
                                float* __restrict__ hr_out,
                                float* __restrict__ out, int out_size)
{
    int l = blockIdx.x;    // 0..255
    int h = blockIdx.y;    // 0..7
    int n = threadIdx.x;   // 0..63
    __shared__ float2 vec[64];
    vec[n] = heig[l*HD + h*64 + n];
    __syncthreads();
    const float* Vr = vr + h*4096 + n*64;
    const float* Vi = vi + h*4096 + n*64;
    float2 acc = make_float2(0.0f, 0.0f);
#pragma unroll 8
    for (int o = 0; o < 64; o++) {
        float mr = Vr[o], mi = Vi[o];
        float2 v = vec[o];
        acc.x += mr*v.x - mi*v.y;
        acc.y += mr*v.y + mi*v.x;
    }
    hr_out[(size_t)l*DIMN + h*128 + n*2]     = acc.x;
    hr_out[(size_t)l*DIMN + h*128 + n*2 + 1] = acc.y;
    if (l == LL-1) {
        if (out_size >= OUT_Y + 2*HD) {
            // interleaved complex (re,im)
            out[OUT_Y + (h*64+n)*2]     = acc.x;
            out[OUT_Y + (h*64+n)*2 + 1] = acc.y;
        } else if (out_size >= OUT_Y + HD) {
            // real part only (complex64 -> float32 astype)
            out[OUT_Y + h*64 + n] = acc.x;
        }
    }
}

// ---------------- launch ---------------------------------------------------
extern "C" void kernel_launch(void* const* d_in, const int* in_sizes, int n_in,
                              void* d_out, int out_size)
{
    const float* x        = (const float*)d_in[0];
    const float* hreal    = (const float*)d_in[1];
    const float* himag    = (const float*)d_in[2];
    const float* w_in1    = (const float*)d_in[3];
    const float* b_in1    = (const float*)d_in[4];
    const float* w_in2    = (const float*)d_in[5];
    const float* b_in2    = (const float*)d_in[6];
    const float* w_out1   = (const float*)d_in[7];
    const float* b_out1   = (const float*)d_in[8];
    const float* w_out2   = (const float*)d_in[9];
    const float* b_out2   = (const float*)d_in[10];
    const float* mvr      = (const float*)d_in[11];
    const float* mvi      = (const float*)d_in[12];
    float* out = (float*)d_out;

    float *t1, *t2, *hr, *y1;
    float2 *xc, *a, *vinv, *w, *heig;
    cudaGetSymbolAddress((void**)&t1,   g_t1);
    cudaGetSymbolAddress((void**)&t2,   g_t2);
    cudaGetSymbolAddress((void**)&xc,   g_xc);
    cudaGetSymbolAddress((void**)&a,    g_a);
    cudaGetSymbolAddress((void**)&vinv, g_vinv);
    cudaGetSymbolAddress((void**)&w,    g_w);
    cudaGetSymbolAddress((void**)&heig, g_heig);
    cudaGetSymbolAddress((void**)&hr,   g_hr);
    cudaGetSymbolAddress((void**)&y1,   g_y1);

    cudaFuncSetAttribute(inv_kernel, cudaFuncAttributeMaxDynamicSharedMemorySize, 65536);

    // t1 = silu(x @ w_in1 + b_in1)
    gemm_kernel<<<dim3(DIMN/BN, LL/BM), 256>>>(x, w_in1, b_in1, t1, LL, DIMN, DIMN, 1);
    // t2 = t1 @ w_in2 + b_in2
    gemm_kernel<<<dim3(2*DIMN/BN, LL/BM), 256>>>(t1, w_in2, b_in2, t2, LL, 2*DIMN, DIMN, 0);
    // split xc / normalized a
    prep_kernel<<<(LL*HD + 255)/256, 256>>>(t2, xc, a);
    // Vinv (independent of the above)
    inv_kernel<<<HH, 256, 65536>>>(mvr, mvi, vinv);
    // w[0..256] = Vinv @ [hidden, xc[0..255]]
    matvec_vinv_kernel<<<dim3(LL+1, HH), 64>>>(vinv, xc, hreal, himag, w);
    // diagonal recurrence
    scan_kernel<<<1, HD>>>(a, w, heig);
    // back to original basis; pack hr; write hidden_next
    matvec_v_kernel<<<dim3(LL, HH), 64>>>(mvr, mvi, heig, hr, out, out_size);
    // y1 = silu(hr @ w_out1 + b_out1)
    gemm_kernel<<<dim3(DIMN/BN, LL/BM), 256>>>(hr, w_out1, b_out1, y1, LL, DIMN, DIMN, 1);
    // y = y1 @ w_out2 + b_out2  -> d_out
    gemm_kernel<<<dim3(DIMN/BN, LL/BM), 256>>>(y1, w_out2, b_out2, out, LL, DIMN, DIMN, 0);
}

// round 4
// speedup vs baseline: 2.5142x; 2.5142x over previous
#include <cuda_runtime.h>
#include <cuda_bf16.h>

// Shapes (fixed by the problem)
#define DIMN 1024
#define HH 8
#define DD 64
#define LL 256
#define HD 512           // H*D
#define OUT_Y (LL*DIMN)  // 262144

// ---------------- scratch (device globals; no allocation allowed) ----------
__device__ float  g_t1[LL*DIMN];
__device__ float  g_t2[LL*DIMN*2];
__device__ float2 g_xc[LL*HD];
__device__ float2 g_a[LL*HD];
__device__ float2 g_vinv[HH*DD*DD];
__device__ float2 g_w[(LL+1)*HD];
__device__ float2 g_heig[LL*HD];
__device__ float  g_hr[LL*DIMN];
__device__ float  g_y1[LL*DIMN];

__device__ __forceinline__ float2 cmulf(float2 a, float2 b) {
    return make_float2(a.x*b.x - a.y*b.y, a.x*b.y + a.y*b.x);
}

// ---------------- tf32 helpers ---------------------------------------------
__device__ __forceinline__ unsigned f2tf32(float x) {
    unsigned r;
    asm("cvt.rna.tf32.f32 %0, %1;" : "=r"(r) : "f"(x));
    return r;
}
__device__ __forceinline__ void mma_tf32(float* c, const unsigned* a, const unsigned* b) {
    asm volatile(
        "mma.sync.aligned.m16n8k8.row.col.f32.tf32.tf32.f32 "
        "{%0,%1,%2,%3}, {%4,%5,%6,%7}, {%8,%9}, {%0,%1,%2,%3};\n"
        : "+f"(c[0]), "+f"(c[1]), "+f"(c[2]), "+f"(c[3])
        : "r"(a[0]), "r"(a[1]), "r"(a[2]), "r"(a[3]), "r"(b[0]), "r"(b[1]));
}

// ---------------- GEMM: C[M,N] = act(A[M,K] @ W[K,N] + bias) ----------------
// Tensor-core tf32 with 3xTF32 hi/lo error compensation (fp32-class accuracy).
// Block tile 64x64, BK=16, 256 threads = 8 warps (2 in M x 4 in N),
// warp tile 32x16, m16n8k8 atoms. Double-buffered smem.
#define APITCH 20   // 64 rows x 20 floats (80B rows -> 16B aligned, conflict-free a-frag)
#define WPITCH 72   // 16 rows x 72 floats (288B rows -> conflict-free b-frag)
__global__ __launch_bounds__(256) void gemm_tc(
    const float* __restrict__ A, const float* __restrict__ W,
    const float* __restrict__ bias, float* __restrict__ C,
    int M, int N, int K, int act)
{
    __shared__ float As[2][64][APITCH];
    __shared__ float Ws[2][16][WPITCH];

    const int tid  = threadIdx.x;
    const int lane = tid & 31;
    const int wid  = tid >> 5;
    const int wm   = wid & 1;      // 0..1  (M)
    const int wn   = wid >> 1;     // 0..3  (N)
    const int g    = lane >> 2;    // 0..7
    const int tig  = lane & 3;     // 0..3

    float acc[2][2][4] = {};

    // gmem load assignments
    const int ar  = tid >> 2;            // 0..63
    const int akq = (tid & 3) << 2;      // 0,4,8,12
    const int wkk = tid >> 4;            // 0..15
    const int wnq = (tid & 15) << 2;     // 0..60
    const float* Ap = A + (size_t)(blockIdx.y*64 + ar)*K + akq;
    const float* Wp = W + (size_t)wkk*N + blockIdx.x*64 + wnq;

    const int nc = K >> 4;

    // prologue: chunk 0 -> buffer 0
    float4 av = *(const float4*)Ap;
    float4 wv = *(const float4*)Wp;
    As[0][ar][akq+0] = av.x; As[0][ar][akq+1] = av.y;
    As[0][ar][akq+2] = av.z; As[0][ar][akq+3] = av.w;
    *(float4*)&Ws[0][wkk][wnq] = wv;
    __syncthreads();

    for (int c = 0; c < nc; c++) {
        const int cur = c & 1;
        if (c + 1 < nc) {
            av = *(const float4*)(Ap + (c+1)*16);
            wv = *(const float4*)(Wp + (size_t)(c+1)*16*N);
        }

        // load + split fragments
        unsigned ahi[2][2][4]; unsigned alo[2][2][4];
        unsigned bhi[2][2][2]; unsigned blo[2][2][2];
#pragma unroll
        for (int ma = 0; ma < 2; ma++)
#pragma unroll
            for (int ka = 0; ka < 2; ka++)
#pragma unroll
                for (int j = 0; j < 4; j++) {
                    int row = wm*32 + ma*16 + g + (j & 1)*8;
                    int col = ka*8 + tig + (j >> 1)*4;
                    float a = As[cur][row][col];
                    unsigned h = f2tf32(a);
                    ahi[ma][ka][j] = h;
                    alo[ma][ka][j] = __float_as_uint(a - __uint_as_float(h));
                }
#pragma unroll
        for (int na = 0; na < 2; na++)
#pragma unroll
            for (int ka = 0; ka < 2; ka++)
#pragma unroll
                for (int j = 0; j < 2; j++) {
                    float b = Ws[cur][ka*8 + tig + j*4][wn*16 + na*8 + g];
                    unsigned h = f2tf32(b);
                    bhi[na][ka][j] = h;
                    blo[na][ka][j] = __float_as_uint(b - __uint_as_float(h));
                }

#pragma unroll
        for (int ma = 0; ma < 2; ma++)
#pragma unroll
            for (int na = 0; na < 2; na++)
#pragma unroll
                for (int ka = 0; ka < 2; ka++) {
                    mma_tf32(acc[ma][na], alo[ma][ka], bhi[na][ka]);
                    mma_tf32(acc[ma][na], ahi[ma][ka], blo[na][ka]);
                    mma_tf32(acc[ma][na], ahi[ma][ka], bhi[na][ka]);
                }

        if (c + 1 < nc) {
            const int nxt = 1 - cur;
            As[nxt][ar][akq+0] = av.x; As[nxt][ar][akq+1] = av.y;
            As[nxt][ar][akq+2] = av.z; As[nxt][ar][akq+3] = av.w;
            *(float4*)&Ws[nxt][wkk][wnq] = wv;
        }
        __syncthreads();
    }

    // epilogue: bias + optional silu, float2 stores
#pragma unroll
    for (int ma = 0; ma < 2; ma++) {
#pragma unroll
        for (int na = 0; na < 2; na++) {
            int row = blockIdx.y*64 + wm*32 + ma*16 + g;
            int col = blockIdx.x*64 + wn*16 + na*8 + 2*tig;
            float b0 = bias[col], b1 = bias[col+1];
            float v0 = acc[ma][na][0] + b0;
            float v1 = acc[ma][na][1] + b1;
            float v2 = acc[ma][na][2] + b0;
            float v3 = acc[ma][na][3] + b1;
            if (act) {
                v0 = v0 / (1.0f + expf(-v0));
                v1 = v1 / (1.0f + expf(-v1));
                v2 = v2 / (1.0f + expf(-v2));
                v3 = v3 / (1.0f + expf(-v3));
            }
            *(float2*)&C[(size_t)row*N + col]     = make_float2(v0, v1);
            *(float2*)&C[(size_t)(row+8)*N + col] = make_float2(v2, v3);
        }
    }
}

// ---------------- prep: split t2 into xc and normalized a ------------------
__global__ void prep_kernel(const float* __restrict__ t2,
                            float2* __restrict__ xc, float2* __restrict__ a)
{
    int e = blockIdx.x*blockDim.x + threadIdx.x;
    if (e >= LL*HD) return;
    int l = e >> 9, hd = e & 511;
    const float* p = t2 + (size_t)l*2048 + hd*4;
    float xr = p[0], xi = p[1], ar = p[2], ai = p[3];
    xc[e] = make_float2(xr, xi);
    float m2 = ar*ar + ai*ai;
    float f = (m2/(1.0f+m2)) * rsqrtf(m2);   // sigmoid(log m2) * rsqrt(m2)
    a[e] = make_float2(ar*f, ai*f);
}

// ---------------- complex 64x64 inverse (Gauss-Jordan, partial pivot) ------
// 512 threads, warp-parallel pivot search, fused swap+scale.
__global__ __launch_bounds__(512) void inv_kernel(
    const float* __restrict__ vr, const float* __restrict__ vi,
    float2* __restrict__ vinv)
{
    extern __shared__ float2 sh[];
    float2* Am = sh;          // 64*64
    float2* Im = sh + 4096;   // 64*64
    __shared__ float2 fac[64];
    __shared__ float2 pivval;
    __shared__ int piv;
    int h = blockIdx.x;
    int t = threadIdx.x;   // 512 threads

    for (int i = t; i < 4096; i += 512) {
        int n = i >> 6, o = i & 63;
        Am[i] = make_float2(vr[h*4096 + i], vi[h*4096 + i]);
        Im[i] = make_float2(n == o ? 1.0f : 0.0f, 0.0f);
    }
    __syncthreads();

    for (int k = 0; k < 64; k++) {
        // warp-parallel pivot search (warp 0)
        if (t < 32) {
            float best = -1.0f; int bp = k;
            for (int r = k + t; r < 64; r += 32) {
                float2 v = Am[r*64+k];
                float m = v.x*v.x + v.y*v.y;
                if (m > best) { best = m; bp = r; }
            }
#pragma unroll
            for (int o = 16; o; o >>= 1) {
                float ob = __shfl_down_sync(0xffffffffu, best, o);
                int  obp = __shfl_down_sync(0xffffffffu, bp,   o);
                if (ob > best) { best = ob; bp = obp; }
            }
            if (t == 0) { piv = bp; pivval = Am[bp*64+k]; }
        }
        __syncthreads();
        const int p = piv;
        const float2 pv = pivval;
        const float im2 = 1.0f/(pv.x*pv.x + pv.y*pv.y);
        const float2 pinv = make_float2(pv.x*im2, -pv.y*im2);

        // fused swap + scale (row p -> row k scaled; old row k -> row p)
        if (t < 128) {
            float2* Mm = (t < 64) ? Am : Im;
            int c = t & 63;
            float2 rp = Mm[p*64+c];
            float2 rk = Mm[k*64+c];
            Mm[k*64+c] = cmulf(rp, pinv);
            if (p != k) Mm[p*64+c] = rk;
        }
        __syncthreads();
        if (t < 64) fac[t] = Am[t*64+k];
        __syncthreads();

        // eliminate: 512 threads -> (matrix, col, row-quarter)
        {
            int c = t & 63;
            float2* Mm = ((t >> 6) & 1) ? Im : Am;
            int rs = t >> 7;                 // 0..3
            float2 pk = Mm[k*64+c];
#pragma unroll 4
            for (int r = rs; r < 64; r += 4) {
                if (r == k) continue;
                float2 f = fac[r];
                float2 v = Mm[r*64+c];
                v.x -= f.x*pk.x - f.y*pk.y;
                v.y -= f.x*pk.y + f.y*pk.x;
                Mm[r*64+c] = v;
            }
        }
        __syncthreads();
    }
    for (int i = t; i < 4096; i += 512) vinv[h*4096 + i] = Im[i];
}

// ---------------- w[li] = Vinv[h] @ x_roll-extended ------------------------
// li = 0 -> hidden; li = 1..256 -> xc[li-1]
__global__ void matvec_vinv_kernel(const float2* __restrict__ vinv,
                                   const float2* __restrict__ xc,
                                   const float* __restrict__ hreal,
                                   const float* __restrict__ himag,
                                   float2* __restrict__ w)
{
    int li = blockIdx.x;   // 0..256
    int h  = blockIdx.y;   // 0..7
    int n  = threadIdx.x;  // 0..63
    __shared__ float2 vec[64];
    if (li == 0) vec[n] = make_float2(hreal[h*64+n], himag[h*64+n]);
    else         vec[n] = xc[(li-1)*HD + h*64 + n];
    __syncthreads();
    const float2* Vh = vinv + h*4096 + n*64;
    float2 acc = make_float2(0.0f, 0.0f);
#pragma unroll 8
    for (int o = 0; o < 64; o++) {
        float2 m = Vh[o], v = vec[o];
        acc.x += m.x*v.x - m.y*v.y;
        acc.y += m.x*v.y + m.y*v.x;
    }
    w[li*HD + h*64 + n] = acc;
}

// ---------------- sequential diagonal recurrence ---------------------------
// s[m] = a[m]*(s[m-1] + w[m]);  heig[m] = s[m] + w[m+1]
__global__ void scan_kernel(const float2* __restrict__ a,
                            const float2* __restrict__ w,
                            float2* __restrict__ heig)
{
    int hd = threadIdx.x;  // 512 threads
    float2 s = make_float2(0.0f, 0.0f);
#pragma unroll 4
    for (int m = 0; m < LL; m++) {
        float2 wm = w[m*HD + hd];
        float2 am = a[m*HD + hd];
        float2 tv = make_float2(s.x + wm.x, s.y + wm.y);
        s = cmulf(am, tv);
        float2 wn = w[(m+1)*HD + hd];
        heig[m*HD + hd] = make_float2(s.x + wn.x, s.y + wn.y);
    }
}

// ---------------- out_h[l] = V[h] @ heig[l]; pack hr; emit hidden_next -----
__global__ void matvec_v_kernel(const float* __restrict__ vr,
                                const float* __restrict__ vi,
                                const float2* __restrict__ heig,
                                float* __restrict__ hr_out,
                                float* __restrict__ out, int out_size)
{
    int l = blockIdx.x;    // 0..255
    int h = blockIdx.y;    // 0..7
    int n = threadIdx.x;   // 0..63
    __shared__ float2 vec[64];
    vec[n] = heig[l*HD + h*64 + n];
    __syncthreads();
    const float* Vr = vr + h*4096 + n*64;
    const float* Vi = vi + h*4096 + n*64;
    float2 acc = make_float2(0.0f, 0.0f);
#pragma unroll 8
    for (int o = 0; o < 64; o++) {
        float mr = Vr[o], mi = Vi[o];
        float2 v = vec[o];
        acc.x += mr*v.x - mi*v.y;
        acc.y += mr*v.y + mi*v.x;
    }
    hr_out[(size_t)l*DIMN + h*128 + n*2]     = acc.x;
    hr_out[(size_t)l*DIMN + h*128 + n*2 + 1] = acc.y;
    if (l == LL-1) {
        if (out_size >= OUT_Y + 2*HD) {
            out[OUT_Y + (h*64+n)*2]     = acc.x;
            out[OUT_Y + (h*64+n)*2 + 1] = acc.y;
        } else if (out_size >= OUT_Y + HD) {
            out[OUT_Y + h*64 + n] = acc.x;
        }
    }
}

// ---------------- launch ---------------------------------------------------
extern "C" void kernel_launch(void* const* d_in, const int* in_sizes, int n_in,
                              void* d_out, int out_size)
{
    const float* x        = (const float*)d_in[0];
    const float* hreal    = (const float*)d_in[1];
    const float* himag    = (const float*)d_in[2];
    const float* w_in1    = (const float*)d_in[3];
    const float* b_in1    = (const float*)d_in[4];
    const float* w_in2    = (const float*)d_in[5];
    const float* b_in2    = (const float*)d_in[6];
    const float* w_out1   = (const float*)d_in[7];
    const float* b_out1   = (const float*)d_in[8];
    const float* w_out2   = (const float*)d_in[9];
    const float* b_out2   = (const float*)d_in[10];
    const float* mvr      = (const float*)d_in[11];
    const float* mvi      = (const float*)d_in[12];
    float* out = (float*)d_out;

    float *t1, *t2, *hr, *y1;
    float2 *xc, *a, *vinv, *w, *heig;
    cudaGetSymbolAddress((void**)&t1,   g_t1);
    cudaGetSymbolAddress((void**)&t2,   g_t2);
    cudaGetSymbolAddress((void**)&xc,   g_xc);
    cudaGetSymbolAddress((void**)&a,    g_a);
    cudaGetSymbolAddress((void**)&vinv, g_vinv);
    cudaGetSymbolAddress((void**)&w,    g_w);
    cudaGetSymbolAddress((void**)&heig, g_heig);
    cudaGetSymbolAddress((void**)&hr,   g_hr);
    cudaGetSymbolAddress((void**)&y1,   g_y1);

    cudaFuncSetAttribute(inv_kernel, cudaFuncAttributeMaxDynamicSharedMemorySize, 65536);

    // Vinv first (independent; cheap now)
    inv_kernel<<<HH, 512, 65536>>>(mvr, mvi, vinv);
    // t1 = silu(x @ w_in1 + b_in1)
    gemm_tc<<<dim3(DIMN/64, LL/64), 256>>>(x, w_in1, b_in1, t1, LL, DIMN, DIMN, 1);
    // t2 = t1 @ w_in2 + b_in2
    gemm_tc<<<dim3(2*DIMN/64, LL/64), 256>>>(t1, w_in2, b_in2, t2, LL, 2*DIMN, DIMN, 0);
    // split xc / normalized a
    prep_kernel<<<(LL*HD + 255)/256, 256>>>(t2, xc, a);
    // w[0..256] = Vinv @ [hidden, xc[0..255]]
    matvec_vinv_kernel<<<dim3(LL+1, HH), 64>>>(vinv, xc, hreal, himag, w);
    // diagonal recurrence
    scan_kernel<<<1, HD>>>(a, w, heig);
    // back to original basis; pack hr; write hidden_next
    matvec_v_kernel<<<dim3(LL, HH), 64>>>(mvr, mvi, heig, hr, out, out_size);
    // y1 = silu(hr @ w_out1 + b_out1)
    gemm_tc<<<dim3(DIMN/64, LL/64), 256>>>(hr, w_out1, b_out1, y1, LL, DIMN, DIMN, 1);
    // y = y1 @ w_out2 + b_out2  -> d_out
    gemm_tc<<<dim3(DIMN/64, LL/64), 256>>>(y1, w_out2, b_out2, out, LL, DIMN, DIMN, 0);
}

// round 5
// speedup vs baseline: 2.8294x; 1.1254x over previous
#include <cuda_runtime.h>
#include <cuda_bf16.h>

// Shapes (fixed by the problem)
#define DIMN 1024
#define HH 8
#define DD 64
#define LL 256
#define HD 512           // H*D
#define OUT_Y (LL*DIMN)  // 262144

// ---------------- scratch (device globals; no allocation allowed) ----------
__device__ float  g_t1[LL*DIMN];
__device__ float  g_part[4*LL*2*DIMN];   // split-K partials (max 4 x 256 x 2048)
__device__ float2 g_xc[LL*HD];
__device__ float2 g_a[LL*HD];
__device__ float2 g_vinv[HH*DD*DD];
__device__ float2 g_w[(LL+1)*HD];
__device__ float2 g_heig[LL*HD];
__device__ float  g_hr[LL*DIMN];
__device__ float  g_y1[LL*DIMN];

__device__ __forceinline__ float2 cmulf(float2 a, float2 b) {
    return make_float2(a.x*b.x - a.y*b.y, a.x*b.y + a.y*b.x);
}

// ---------------- tf32 helpers ---------------------------------------------
__device__ __forceinline__ unsigned f2tf32(float x) {
    unsigned r;
    asm("cvt.rna.tf32.f32 %0, %1;" : "=r"(r) : "f"(x));
    return r;
}
__device__ __forceinline__ void mma_tf32(float* c, const unsigned* a, const unsigned* b) {
    asm volatile(
        "mma.sync.aligned.m16n8k8.row.col.f32.tf32.tf32.f32 "
        "{%0,%1,%2,%3}, {%4,%5,%6,%7}, {%8,%9}, {%0,%1,%2,%3};\n"
        : "+f"(c[0]), "+f"(c[1]), "+f"(c[2]), "+f"(c[3])
        : "r"(a[0]), "r"(a[1]), "r"(a[2]), "r"(a[3]), "r"(b[0]), "r"(b[1]));
}

// ---------------- split-K GEMM partials: P[kc] = A[:,kc] @ W[kc,:] ----------
// Tensor-core tf32 with 3xTF32 hi/lo compensation. Block tile 64x64, BK=16,
// 256 threads = 8 warps (2 M x 4 N), warp tile 32x16. Double-buffered smem.
// grid = (N/64, M/64, KSPLITS); each z-slice covers K/KSPLITS of the K dim
// and writes its 64x64 partial tile into P + z*M*N.
#define APITCH 20
#define WPITCH 72
__global__ __launch_bounds__(256) void gemm_tc_sk(
    const float* __restrict__ A, const float* __restrict__ W,
    float* __restrict__ P, int M, int N, int K, int ksplit)
{
    __shared__ float As[2][64][APITCH];
    __shared__ float Ws[2][16][WPITCH];

    const int tid  = threadIdx.x;
    const int lane = tid & 31;
    const int wid  = tid >> 5;
    const int wm   = wid & 1;
    const int wn   = wid >> 1;
    const int g    = lane >> 2;
    const int tig  = lane & 3;

    const int ksub = K / ksplit;
    const int k0g  = blockIdx.z * ksub;

    float acc[2][2][4] = {};

    const int ar  = tid >> 2;
    const int akq = (tid & 3) << 2;
    const int wkk = tid >> 4;
    const int wnq = (tid & 15) << 2;
    const float* Ap = A + (size_t)(blockIdx.y*64 + ar)*K + k0g + akq;
    const float* Wp = W + (size_t)(k0g + wkk)*N + blockIdx.x*64 + wnq;

    const int nc = ksub >> 4;

    float4 av = *(const float4*)Ap;
    float4 wv = *(const float4*)Wp;
    As[0][ar][akq+0] = av.x; As[0][ar][akq+1] = av.y;
    As[0][ar][akq+2] = av.z; As[0][ar][akq+3] = av.w;
    *(float4*)&Ws[0][wkk][wnq] = wv;
    __syncthreads();

    for (int c = 0; c < nc; c++) {
        const int cur = c & 1;
        if (c + 1 < nc) {
            av = *(const float4*)(Ap + (c+1)*16);
            wv = *(const float4*)(Wp + (size_t)(c+1)*16*N);
        }

        unsigned ahi[2][2][4]; unsigned alo[2][2][4];
        unsigned bhi[2][2][2]; unsigned blo[2][2][2];
#pragma unroll
        for (int ma = 0; ma < 2; ma++)
#pragma unroll
            for (int ka = 0; ka < 2; ka++)
#pragma unroll
                for (int j = 0; j < 4; j++) {
                    int row = wm*32 + ma*16 + g + (j & 1)*8;
                    int col = ka*8 + tig + (j >> 1)*4;
                    float a = As[cur][row][col];
                    unsigned h = f2tf32(a);
                    ahi[ma][ka][j] = h;
                    alo[ma][ka][j] = __float_as_uint(a - __uint_as_float(h));
                }
#pragma unroll
        for (int na = 0; na < 2; na++)
#pragma unroll
            for (int ka = 0; ka < 2; ka++)
#pragma unroll
                for (int j = 0; j < 2; j++) {
                    float b = Ws[cur][ka*8 + tig + j*4][wn*16 + na*8 + g];
                    unsigned h = f2tf32(b);
                    bhi[na][ka][j] = h;
                    blo[na][ka][j] = __float_as_uint(b - __uint_as_float(h));
                }

#pragma unroll
        for (int ma = 0; ma < 2; ma++)
#pragma unroll
            for (int na = 0; na < 2; na++)
#pragma unroll
                for (int ka = 0; ka < 2; ka++) {
                    mma_tf32(acc[ma][na], alo[ma][ka], bhi[na][ka]);
                    mma_tf32(acc[ma][na], ahi[ma][ka], blo[na][ka]);
                    mma_tf32(acc[ma][na], ahi[ma][ka], bhi[na][ka]);
                }

        if (c + 1 < nc) {
            const int nxt = 1 - cur;
            As[nxt][ar][akq+0] = av.x; As[nxt][ar][akq+1] = av.y;
            As[nxt][ar][akq+2] = av.z; As[nxt][ar][akq+3] = av.w;
            *(float4*)&Ws[nxt][wkk][wnq] = wv;
        }
        __syncthreads();
    }

    float* Pz = P + (size_t)blockIdx.z * M * N;
#pragma unroll
    for (int ma = 0; ma < 2; ma++) {
#pragma unroll
        for (int na = 0; na < 2; na++) {
            int row = blockIdx.y*64 + wm*32 + ma*16 + g;
            int col = blockIdx.x*64 + wn*16 + na*8 + 2*tig;
            *(float2*)&Pz[(size_t)row*N + col]     = make_float2(acc[ma][na][0], acc[ma][na][1]);
            *(float2*)&Pz[(size_t)(row+8)*N + col] = make_float2(acc[ma][na][2], acc[ma][na][3]);
        }
    }
}

// ---------------- reduce split-K partials + bias (+silu) -------------------
__global__ void reduce_kernel(const float* __restrict__ P,
                              const float* __restrict__ bias,
                              float* __restrict__ C,
                              int MN, int N, int ksplit, int act)
{
    int e = (blockIdx.x*blockDim.x + threadIdx.x) * 4;
    if (e >= MN) return;
    float4 s = *(const float4*)(P + e);
    for (int z = 1; z < ksplit; z++) {
        float4 p = *(const float4*)(P + (size_t)z*MN + e);
        s.x += p.x; s.y += p.y; s.z += p.z; s.w += p.w;
    }
    int c = e % N;
    float4 b = *(const float4*)(bias + c);
    s.x += b.x; s.y += b.y; s.z += b.z; s.w += b.w;
    if (act) {
        s.x = s.x / (1.0f + expf(-s.x));
        s.y = s.y / (1.0f + expf(-s.y));
        s.z = s.z / (1.0f + expf(-s.z));
        s.w = s.w / (1.0f + expf(-s.w));
    }
    *(float4*)(C + e) = s;
}

// ---------------- reduce partials of GEMM2 and emit xc + normalized a ------
// t2 row l, cols [4hd..4hd+3] = (xr, xi, ar, ai) for channel hd.
__global__ void reduce_prep_kernel(const float* __restrict__ P,
                                   const float* __restrict__ bias,
                                   float2* __restrict__ xc, float2* __restrict__ a,
                                   int ksplit)
{
    int e = blockIdx.x*blockDim.x + threadIdx.x;   // 0 .. LL*HD-1
    if (e >= LL*HD) return;
    const int MN = LL * 2 * DIMN;
    int off = e * 4;
    float4 s = *(const float4*)(P + off);
    for (int z = 1; z < ksplit; z++) {
        float4 p = *(const float4*)(P + (size_t)z*MN + off);
        s.x += p.x; s.y += p.y; s.z += p.z; s.w += p.w;
    }
    int c = off % (2*DIMN);
    float4 b = *(const float4*)(bias + c);
    float xr = s.x + b.x, xi = s.y + b.y, ar = s.z + b.z, ai = s.w + b.w;
    xc[e] = make_float2(xr, xi);
    float m2 = ar*ar + ai*ai;
    float f = (m2/(1.0f+m2)) * rsqrtf(m2);   // sigmoid(log m2) * rsqrt(m2)
    a[e] = make_float2(ar*f, ai*f);
}

// ---------------- complex 64x64 inverse (Gauss-Jordan, partial pivot) ------
__global__ __launch_bounds__(512) void inv_kernel(
    const float* __restrict__ vr, const float* __restrict__ vi,
    float2* __restrict__ vinv)
{
    extern __shared__ float2 sh[];
    float2* Am = sh;          // 64*64
    float2* Im = sh + 4096;   // 64*64
    __shared__ float2 fac[64];
    __shared__ float2 pivval;
    __shared__ int piv;
    int h = blockIdx.x;
    int t = threadIdx.x;   // 512 threads

    for (int i = t; i < 4096; i += 512) {
        int n = i >> 6, o = i & 63;
        Am[i] = make_float2(vr[h*4096 + i], vi[h*4096 + i]);
        Im[i] = make_float2(n == o ? 1.0f : 0.0f, 0.0f);
    }
    __syncthreads();

    for (int k = 0; k < 64; k++) {
        if (t < 32) {
            float best = -1.0f; int bp = k;
            for (int r = k + t; r < 64; r += 32) {
                float2 v = Am[r*64+k];
                float m = v.x*v.x + v.y*v.y;
                if (m > best) { best = m; bp = r; }
            }
#pragma unroll
            for (int o = 16; o; o >>= 1) {
                float ob = __shfl_down_sync(0xffffffffu, best, o);
                int  obp = __shfl_down_sync(0xffffffffu, bp,   o);
                if (ob > best) { best = ob; bp = obp; }
            }
            if (t == 0) { piv = bp; pivval = Am[bp*64+k]; }
        }
        __syncthreads();
        const int p = piv;
        const float2 pv = pivval;
        const float im2 = 1.0f/(pv.x*pv.x + pv.y*pv.y);
        const float2 pinv = make_float2(pv.x*im2, -pv.y*im2);

        if (t < 128) {
            float2* Mm = (t < 64) ? Am : Im;
            int c = t & 63;
            float2 rp = Mm[p*64+c];
            float2 rk = Mm[k*64+c];
            Mm[k*64+c] = cmulf(rp, pinv);
            if (p != k) Mm[p*64+c] = rk;
        }
        __syncthreads();
        if (t < 64) fac[t] = Am[t*64+k];
        __syncthreads();

        {
            int c = t & 63;
            float2* Mm = ((t >> 6) & 1) ? Im : Am;
            int rs = t >> 7;
            float2 pk = Mm[k*64+c];
#pragma unroll 4
            for (int r = rs; r < 64; r += 4) {
                if (r == k) continue;
                float2 f = fac[r];
                float2 v = Mm[r*64+c];
                v.x -= f.x*pk.x - f.y*pk.y;
                v.y -= f.x*pk.y + f.y*pk.x;
                Mm[r*64+c] = v;
            }
        }
        __syncthreads();
    }
    for (int i = t; i < 4096; i += 512) vinv[h*4096 + i] = Im[i];
}

// ---------------- w[li] = Vinv[h] @ x_roll-extended ------------------------
__global__ void matvec_vinv_kernel(const float2* __restrict__ vinv,
                                   const float2* __restrict__ xc,
                                   const float* __restrict__ hreal,
                                   const float* __restrict__ himag,
                                   float2* __restrict__ w)
{
    int li = blockIdx.x;   // 0..256
    int h  = blockIdx.y;   // 0..7
    int n  = threadIdx.x;  // 0..63
    __shared__ float2 vec[64];
    if (li == 0) vec[n] = make_float2(hreal[h*64+n], himag[h*64+n]);
    else         vec[n] = xc[(li-1)*HD + h*64 + n];
    __syncthreads();
    const float2* Vh = vinv + h*4096 + n*64;
    float2 acc = make_float2(0.0f, 0.0f);
#pragma unroll 8
    for (int o = 0; o < 64; o++) {
        float2 m = Vh[o], v = vec[o];
        acc.x += m.x*v.x - m.y*v.y;
        acc.y += m.x*v.y + m.y*v.x;
    }
    w[li*HD + h*64 + n] = acc;
}

// ---------------- sequential diagonal recurrence ---------------------------
__global__ void scan_kernel(const float2* __restrict__ a,
                            const float2* __restrict__ w,
                            float2* __restrict__ heig)
{
    int hd = threadIdx.x;  // 512 threads
    float2 s = make_float2(0.0f, 0.0f);
#pragma unroll 4
    for (int m = 0; m < LL; m++) {
        float2 wm = w[m*HD + hd];
        float2 am = a[m*HD + hd];
        float2 tv = make_float2(s.x + wm.x, s.y + wm.y);
        s = cmulf(am, tv);
        float2 wn = w[(m+1)*HD + hd];
        heig[m*HD + hd] = make_float2(s.x + wn.x, s.y + wn.y);
    }
}

// ---------------- out_h[l] = V[h] @ heig[l]; pack hr; emit hidden_next -----
__global__ void matvec_v_kernel(const float* __restrict__ vr,
                                const float* __restrict__ vi,
                                const float2* __restrict__ heig,
                                float* __restrict__ hr_out,
                                float* __restrict__ out, int out_size)
{
    int l = blockIdx.x;    // 0..255
    int h = blockIdx.y;    // 0..7
    int n = threadIdx.x;   // 0..63
    __shared__ float2 vec[64];
    vec[n] = heig[l*HD + h*64 + n];
    __syncthreads();
    const float* Vr = vr + h*4096 + n*64;
    const float* Vi = vi + h*4096 + n*64;
    float2 acc = make_float2(0.0f, 0.0f);
#pragma unroll 8
    for (int o = 0; o < 64; o++) {
        float mr = Vr[o], mi = Vi[o];
        float2 v = vec[o];
        acc.x += mr*v.x - mi*v.y;
        acc.y += mr*v.y + mi*v.x;
    }
    hr_out[(size_t)l*DIMN + h*128 + n*2]     = acc.x;
    hr_out[(size_t)l*DIMN + h*128 + n*2 + 1] = acc.y;
    if (l == LL-1) {
        if (out_size >= OUT_Y + 2*HD) {
            out[OUT_Y + (h*64+n)*2]     = acc.x;
            out[OUT_Y + (h*64+n)*2 + 1] = acc.y;
        } else if (out_size >= OUT_Y + HD) {
            out[OUT_Y + h*64 + n] = acc.x;
        }
    }
}

// ---------------- launch ---------------------------------------------------
extern "C" void kernel_launch(void* const* d_in, const int* in_sizes, int n_in,
                              void* d_out, int out_size)
{
    const float* x        = (const float*)d_in[0];
    const float* hreal    = (const float*)d_in[1];
    const float* himag    = (const float*)d_in[2];
    const float* w_in1    = (const float*)d_in[3];
    const float* b_in1    = (const float*)d_in[4];
    const float* w_in2    = (const float*)d_in[5];
    const float* b_in2    = (const float*)d_in[6];
    const float* w_out1   = (const float*)d_in[7];
    const float* b_out1   = (const float*)d_in[8];
    const float* w_out2   = (const float*)d_in[9];
    const float* b_out2   = (const float*)d_in[10];
    const float* mvr      = (const float*)d_in[11];
    const float* mvi      = (const float*)d_in[12];
    float* out = (float*)d_out;

    float *t1, *part, *hr, *y1;
    float2 *xc, *a, *vinv, *w, *heig;
    cudaGetSymbolAddress((void**)&t1,   g_t1);
    cudaGetSymbolAddress((void**)&part, g_part);
    cudaGetSymbolAddress((void**)&xc,   g_xc);
    cudaGetSymbolAddress((void**)&a,    g_a);
    cudaGetSymbolAddress((void**)&vinv, g_vinv);
    cudaGetSymbolAddress((void**)&w,    g_w);
    cudaGetSymbolAddress((void**)&heig, g_heig);
    cudaGetSymbolAddress((void**)&hr,   g_hr);
    cudaGetSymbolAddress((void**)&y1,   g_y1);

    cudaFuncSetAttribute(inv_kernel, cudaFuncAttributeMaxDynamicSharedMemorySize, 65536);

    const int MN1 = LL * DIMN;       // 262144
    const int MN2 = LL * 2 * DIMN;   // 524288

    // Vinv (independent)
    inv_kernel<<<HH, 512, 65536>>>(mvr, mvi, vinv);

    // t1 = silu(x @ w_in1 + b_in1)   split-K=4
    gemm_tc_sk<<<dim3(DIMN/64, LL/64, 4), 256>>>(x, w_in1, part, LL, DIMN, DIMN, 4);
    reduce_kernel<<<(MN1/4 + 255)/256, 256>>>(part, b_in1, t1, MN1, DIMN, 4, 1);

    // t2 partials = t1 @ w_in2 ; fused reduce -> xc, a   split-K=2
    gemm_tc_sk<<<dim3(2*DIMN/64, LL/64, 2), 256>>>(t1, w_in2, part, LL, 2*DIMN, DIMN, 2);
    reduce_prep_kernel<<<(LL*HD + 255)/256, 256>>>(part, b_in2, xc, a, 2);

    // w[0..256] = Vinv @ [hidden, xc[0..255]]
    matvec_vinv_kernel<<<dim3(LL+1, HH), 64>>>(vinv, xc, hreal, himag, w);
    // diagonal recurrence
    scan_kernel<<<1, HD>>>(a, w, heig);
    // back to original basis; pack hr; write hidden_next
    matvec_v_kernel<<<dim3(LL, HH), 64>>>(mvr, mvi, heig, hr, out, out_size);

    // y1 = silu(hr @ w_out1 + b_out1)   split-K=4
    gemm_tc_sk<<<dim3(DIMN/64, LL/64, 4), 256>>>(hr, w_out1, part, LL, DIMN, DIMN, 4);
    reduce_kernel<<<(MN1/4 + 255)/256, 256>>>(part, b_out1, y1, MN1, DIMN, 4, 1);

    // y = y1 @ w_out2 + b_out2 -> d_out   split-K=4
    gemm_tc_sk<<<dim3(DIMN/64, LL/64, 4), 256>>>(y1, w_out2, part, LL, DIMN, DIMN, 4);
    reduce_kernel<<<(MN1/4 + 255)/256, 256>>>(part, b_out2, out, MN1, DIMN, 4, 0);
}

// round 8
// speedup vs baseline: 3.8775x; 1.3705x over previous
#include <cuda_runtime.h>
#include <cuda_bf16.h>

// Shapes (fixed by the problem)
#define DIMN 1024
#define HH 8
#define DD 64
#define LL 256
#define HD 512           // H*D
#define OUT_Y (LL*DIMN)  // 262144

// ---------------- scratch (device globals; no allocation allowed) ----------
__device__ float  g_t1[LL*DIMN];
__device__ float  g_part[8*LL*DIMN];     // split-K partials (8MB)
__device__ float2 g_xc[LL*HD];
__device__ float2 g_a[LL*HD];
__device__ float2 g_vinv[HH*DD*DD];
__device__ float2 g_w[(LL+1)*HD];
__device__ float2 g_heig[LL*HD];
__device__ float  g_hr[LL*DIMN];
__device__ float  g_y1[LL*DIMN];
__device__ float2 g_sP[16*HD];
__device__ float2 g_sQ[16*HD];
__device__ float2 g_sIn[16*HD];

__device__ __forceinline__ float2 cmulf(float2 a, float2 b) {
    return make_float2(a.x*b.x - a.y*b.y, a.x*b.y + a.y*b.x);
}

// ---------------- tf32 helpers ---------------------------------------------
__device__ __forceinline__ unsigned f2tf32(float x) {
    unsigned r;
    asm("cvt.rna.tf32.f32 %0, %1;" : "=r"(r) : "f"(x));
    return r;
}
__device__ __forceinline__ void mma_tf32(float* c, const unsigned* a, const unsigned* b) {
    asm volatile(
        "mma.sync.aligned.m16n8k8.row.col.f32.tf32.tf32.f32 "
        "{%0,%1,%2,%3}, {%4,%5,%6,%7}, {%8,%9}, {%0,%1,%2,%3};\n"
        : "+f"(c[0]), "+f"(c[1]), "+f"(c[2]), "+f"(c[3])
        : "r"(a[0]), "r"(a[1]), "r"(a[2]), "r"(a[3]), "r"(b[0]), "r"(b[1]));
}
// split a float into tf32-hi + fp32 residual (raw bits used as tf32-lo)
__device__ __forceinline__ void splitf(float v, unsigned& h, unsigned& l) {
    h = f2tf32(v);
    l = __float_as_uint(v - __uint_as_float(h));
}

// ---------------- split-K GEMM partials: P[z] = A[:,kz] @ W[kz,:] -----------
// Block tile 64x128, BK=16, 256 threads = 8 warps (2 M x 4 N), warp tile 32x32.
// hi/lo tf32 split done ONCE at smem store; inner loop = LDS + MMA only.
#define APAD 20    // A row pitch (16+4 words)
#define BPAD 136   // B row pitch (128+8 words) -> conflict-free b-frag reads
__global__ __launch_bounds__(256) void gemm_tc_sk(
    const float* __restrict__ A, const float* __restrict__ W,
    float* __restrict__ P, int M, int N, int K, int ksplit)
{
    __shared__ unsigned Ah[64][APAD], Al[64][APAD];
    __shared__ unsigned Bh[16][BPAD], Bl[16][BPAD];

    const int tid  = threadIdx.x;
    const int lane = tid & 31;
    const int wid  = tid >> 5;
    const int wm   = wid & 1;      // 0..1 (M)
    const int wn   = wid >> 1;     // 0..3 (N)
    const int g    = lane >> 2;    // 0..7
    const int tig  = lane & 3;     // 0..3

    const int ksub = K / ksplit;
    const int k0g  = blockIdx.z * ksub;
    const int nc   = ksub >> 4;

    float acc[2][4][4] = {};

    const int ar = tid >> 2;           // 0..63
    const int ac = (tid & 3) << 2;     // 0,4,8,12
    const int br = tid >> 4;           // 0..15
    const int bc = (tid & 15) << 3;    // 0..120 step 8

    const float* Ap = A + (size_t)(blockIdx.y*64 + ar)*K + k0g + ac;
    const float* Wp = W + (size_t)(k0g + br)*N + blockIdx.x*128 + bc;

    float4 av  = *(const float4*)Ap;
    float4 wv0 = *(const float4*)Wp;
    float4 wv1 = *(const float4*)(Wp + 4);

    for (int c = 0; c < nc; c++) {
        if (c) __syncthreads();
        // ---- split-at-store ----
        {
            uint4 h4, l4;
            splitf(av.x, h4.x, l4.x); splitf(av.y, h4.y, l4.y);
            splitf(av.z, h4.z, l4.z); splitf(av.w, h4.w, l4.w);
            *(uint4*)&Ah[ar][ac] = h4; *(uint4*)&Al[ar][ac] = l4;
            splitf(wv0.x, h4.x, l4.x); splitf(wv0.y, h4.y, l4.y);
            splitf(wv0.z, h4.z, l4.z); splitf(wv0.w, h4.w, l4.w);
            *(uint4*)&Bh[br][bc] = h4; *(uint4*)&Bl[br][bc] = l4;
            splitf(wv1.x, h4.x, l4.x); splitf(wv1.y, h4.y, l4.y);
            splitf(wv1.z, h4.z, l4.z); splitf(wv1.w, h4.w, l4.w);
            *(uint4*)&Bh[br][bc+4] = h4; *(uint4*)&Bl[br][bc+4] = l4;
        }
        __syncthreads();
        if (c + 1 < nc) {
            av  = *(const float4*)(Ap + (c+1)*16);
            wv0 = *(const float4*)(Wp + (size_t)(c+1)*16*N);
            wv1 = *(const float4*)(Wp + (size_t)(c+1)*16*N + 4);
        }

        // ---- A fragments (both halves of split) ----
        unsigned ah[2][2][4], al_[2][2][4];
#pragma unroll
        for (int ma = 0; ma < 2; ma++)
#pragma unroll
            for (int ka = 0; ka < 2; ka++)
#pragma unroll
                for (int j = 0; j < 4; j++) {
                    int row = wm*32 + ma*16 + g + (j & 1)*8;
                    int col = ka*8 + tig + (j >> 1)*4;
                    ah[ma][ka][j]  = Ah[row][col];
                    al_[ma][ka][j] = Al[row][col];
                }

        // ---- per-na: load B frags, fire MMAs ----
#pragma unroll
        for (int na = 0; na < 4; na++) {
            unsigned bh[2][2], bl[2][2];
#pragma unroll
            for (int ka = 0; ka < 2; ka++)
#pragma unroll
                for (int j = 0; j < 2; j++) {
                    int r  = ka*8 + tig + j*4;
                    int cc = wn*32 + na*8 + g;
                    bh[ka][j] = Bh[r][cc];
                    bl[ka][j] = Bl[r][cc];
                }
#pragma unroll
            for (int ma = 0; ma < 2; ma++)
#pragma unroll
                for (int ka = 0; ka < 2; ka++) {
                    mma_tf32(acc[ma][na], al_[ma][ka], bh[ka]);
                    mma_tf32(acc[ma][na], ah[ma][ka],  bl[ka]);
                    mma_tf32(acc[ma][na], ah[ma][ka],  bh[ka]);
                }
        }
        if (c + 1 == nc) break;
    }

    float* Pz = P + (size_t)blockIdx.z * M * N;
#pragma unroll
    for (int ma = 0; ma < 2; ma++) {
#pragma unroll
        for (int na = 0; na < 4; na++) {
            int row = blockIdx.y*64 + wm*32 + ma*16 + g;
            int col = blockIdx.x*128 + wn*32 + na*8 + 2*tig;
            *(float2*)&Pz[(size_t)row*N + col]     = make_float2(acc[ma][na][0], acc[ma][na][1]);
            *(float2*)&Pz[(size_t)(row+8)*N + col] = make_float2(acc[ma][na][2], acc[ma][na][3]);
        }
    }
}

// ---------------- reduce split-K partials + bias (+silu) -------------------
__global__ void reduce_kernel(const float* __restrict__ P,
                              const float* __restrict__ bias,
                              float* __restrict__ C,
                              int MN, int N, int ksplit, int act)
{
    int e = (blockIdx.x*blockDim.x + threadIdx.x) * 4;
    if (e >= MN) return;
    float4 s = *(const float4*)(P + e);
    for (int z = 1; z < ksplit; z++) {
        float4 p = *(const float4*)(P + (size_t)z*MN + e);
        s.x += p.x; s.y += p.y; s.z += p.z; s.w += p.w;
    }
    int c = e % N;
    float4 b = *(const float4*)(bias + c);
    s.x += b.x; s.y += b.y; s.z += b.z; s.w += b.w;
    if (act) {
        s.x = s.x / (1.0f + expf(-s.x));
        s.y = s.y / (1.0f + expf(-s.y));
        s.z = s.z / (1.0f + expf(-s.z));
        s.w = s.w / (1.0f + expf(-s.w));
    }
    *(float4*)(C + e) = s;
}

// ---------------- reduce partials of GEMM2 and emit xc + normalized a ------
__global__ void reduce_prep_kernel(const float* __restrict__ P,
                                   const float* __restrict__ bias,
                                   float2* __restrict__ xc, float2* __restrict__ a,
                                   int ksplit)
{
    int e = blockIdx.x*blockDim.x + threadIdx.x;   // 0 .. LL*HD-1
    if (e >= LL*HD) return;
    const int MN = LL * 2 * DIMN;
    int off = e * 4;
    float4 s = *(const float4*)(P + off);
    for (int z = 1; z < ksplit; z++) {
        float4 p = *(const float4*)(P + (size_t)z*MN + off);
        s.x += p.x; s.y += p.y; s.z += p.z; s.w += p.w;
    }
    int c = off % (2*DIMN);
    float4 b = *(const float4*)(bias + c);
    float xr = s.x + b.x, xi = s.y + b.y, ar = s.z + b.z, ai = s.w + b.w;
    xc[e] = make_float2(xr, xi);
    float m2 = ar*ar + ai*ai;
    float f = (m2/(1.0f+m2)) * rsqrtf(m2);   // sigmoid(log m2) * rsqrt(m2)
    a[e] = make_float2(ar*f, ai*f);
}

// ---------------- complex 64x64 inverse (Gauss-Jordan, partial pivot) ------
__global__ __launch_bounds__(512) void inv_kernel(
    const float* __restrict__ vr, const float* __restrict__ vi,
    float2* __restrict__ vinv)
{
    extern __shared__ float2 sh[];
    float2* Am = sh;          // 64*64
    float2* Im = sh + 4096;   // 64*64
    __shared__ float2 fac[64];
    __shared__ float2 pivval;
    __shared__ int piv;
    int h = blockIdx.x;
    int t = threadIdx.x;   // 512 threads

    for (int i = t; i < 4096; i += 512) {
        int n = i >> 6, o = i & 63;
        Am[i] = make_float2(vr[h*4096 + i], vi[h*4096 + i]);
        Im[i] = make_float2(n == o ? 1.0f : 0.0f, 0.0f);
    }
    __syncthreads();

    for (int k = 0; k < 64; k++) {
        if (t < 32) {
            float best = -1.0f; int bp = k;
            for (int r = k + t; r < 64; r += 32) {
                float2 v = Am[r*64+k];
                float m = v.x*v.x + v.y*v.y;
                if (m > best) { best = m; bp = r; }
            }
#pragma unroll
            for (int o = 16; o; o >>= 1) {
                float ob = __shfl_down_sync(0xffffffffu, best, o);
                int  obp = __shfl_down_sync(0xffffffffu, bp,   o);
                if (ob > best) { best = ob; bp = obp; }
            }
            if (t == 0) { piv = bp; pivval = Am[bp*64+k]; }
        }
        __syncthreads();
        const int p = piv;
        const float2 pv = pivval;
        const float im2 = 1.0f/(pv.x*pv.x + pv.y*pv.y);
        const float2 pinv = make_float2(pv.x*im2, -pv.y*im2);

        if (t < 128) {
            float2* Mm = (t < 64) ? Am : Im;
            int c = t & 63;
            float2 rp = Mm[p*64+c];
            float2 rk = Mm[k*64+c];
            Mm[k*64+c] = cmulf(rp, pinv);
            if (p != k) Mm[p*64+c] = rk;
        }
        __syncthreads();
        if (t < 64) fac[t] = Am[t*64+k];
        __syncthreads();

        {
            int c = t & 63;
            float2* Mm = ((t >> 6) & 1) ? Im : Am;
            int rs = t >> 7;
            float2 pk = Mm[k*64+c];
#pragma unroll 4
            for (int r = rs; r < 64; r += 4) {
                if (r == k) continue;
                float2 f = fac[r];
                float2 v = Mm[r*64+c];
                v.x -= f.x*pk.x - f.y*pk.y;
                v.y -= f.x*pk.y + f.y*pk.x;
                Mm[r*64+c] = v;
            }
        }
        __syncthreads();
    }
    for (int i = t; i < 4096; i += 512) vinv[h*4096 + i] = Im[i];
}

// ---------------- tiled matvec: w[li] = Vinv[h] @ [hidden | xc[li-1]] ------
// One CTA per (32-li chunk, head). Vinv cached in smem (coalesced load).
__global__ __launch_bounds__(256) void matvec_vinv_t(
    const float2* __restrict__ vinv, const float2* __restrict__ xc,
    const float* __restrict__ hreal, const float* __restrict__ himag,
    float2* __restrict__ w)
{
    __shared__ float2 Vs[64*65];
    __shared__ float2 vecs[4][64];
    const int lc = blockIdx.x;   // 0..8
    const int h  = blockIdx.y;
    const int tid = threadIdx.x;
    for (int i = tid; i < 4096; i += 256) {
        int n = i >> 6, o = i & 63;
        Vs[n*65 + o] = vinv[h*4096 + i];
    }
    __syncthreads();
    const int g64 = tid >> 6;    // 0..3
    const int n   = tid & 63;
    for (int rep = 0; rep < 8; rep++) {
        int li = lc*32 + rep*4 + g64;
        if (li <= LL) {
            if (li == 0) vecs[g64][n] = make_float2(hreal[h*64+n], himag[h*64+n]);
            else         vecs[g64][n] = xc[(li-1)*HD + h*64 + n];
        }
        __syncthreads();
        if (li <= LL) {
            float2 acc = make_float2(0.0f, 0.0f);
#pragma unroll 8
            for (int o = 0; o < 64; o++) {
                float2 m = Vs[n*65 + o], v = vecs[g64][o];
                acc.x += m.x*v.x - m.y*v.y;
                acc.y += m.x*v.y + m.y*v.x;
            }
            w[li*HD + h*64 + n] = acc;
        }
        __syncthreads();
    }
}

// ---------------- chunked scan: s[m] = a[m]*(s[m-1]+w[m]) ------------------
// Phase A: per (chunk, channel) local (P = prod a, Q = result with s_in=0)
__global__ void scanA_kernel(const float2* __restrict__ a,
                             const float2* __restrict__ w,
                             float2* __restrict__ sP, float2* __restrict__ sQ)
{
    int c = blockIdx.x;      // 0..15
    int hd = threadIdx.x;    // 0..511
    float2 Pp = make_float2(1.0f, 0.0f);
    float2 S  = make_float2(0.0f, 0.0f);
#pragma unroll
    for (int i = 0; i < 16; i++) {
        int m = c*16 + i;
        float2 wm = w[m*HD + hd];
        float2 am = a[m*HD + hd];
        float2 t = make_float2(S.x + wm.x, S.y + wm.y);
        S  = cmulf(am, t);
        Pp = cmulf(am, Pp);
    }
    sP[c*HD + hd] = Pp;
    sQ[c*HD + hd] = S;
}
// Phase B: combine 16 chunk summaries sequentially -> incoming state per chunk
__global__ void scanB_kernel(const float2* __restrict__ sP,
                             const float2* __restrict__ sQ,
                             float2* __restrict__ sIn)
{
    int hd = threadIdx.x;
    float2 s = make_float2(0.0f, 0.0f);
#pragma unroll
    for (int c = 0; c < 16; c++) {
        sIn[c*HD + hd] = s;
        float2 p = sP[c*HD + hd];
        float2 q = sQ[c*HD + hd];
        float2 t = cmulf(p, s);
        s = make_float2(t.x + q.x, t.y + q.y);
    }
}
// Phase C: re-expand with true incoming state; emit heig[m] = s + w[m+1]
__global__ void scanC_kernel(const float2* __restrict__ a,
                             const float2* __restrict__ w,
                             const float2* __restrict__ sIn,
                             float2* __restrict__ heig)
{
    int c = blockIdx.x;
    int hd = threadIdx.x;
    float2 s = sIn[c*HD + hd];
#pragma unroll
    for (int i = 0; i < 16; i++) {
        int m = c*16 + i;
        float2 wm = w[m*HD + hd];
        float2 am = a[m*HD + hd];
        float2 t = make_float2(s.x + wm.x, s.y + wm.y);
        s = cmulf(am, t);
        float2 wn = w[(m+1)*HD + hd];
        heig[m*HD + hd] = make_float2(s.x + wn.x, s.y + wn.y);
    }
}

// ---------------- tiled matvec: out_h[l] = V[h] @ heig[l]; pack hr ---------
__global__ __launch_bounds__(256) void matvec_v_t(
    const float* __restrict__ vr, const float* __restrict__ vi,
    const float2* __restrict__ heig,
    float* __restrict__ hr_out, float* __restrict__ out, int out_size)
{
    __shared__ float2 Vs[64*65];
    __shared__ float2 vecs[4][64];
    const int lc = blockIdx.x;   // 0..7
    const int h  = blockIdx.y;
    const int tid = threadIdx.x;
    for (int i = tid; i < 4096; i += 256) {
        int n = i >> 6, o = i & 63;
        Vs[n*65 + o] = make_float2(vr[h*4096 + i], vi[h*4096 + i]);
    }
    __syncthreads();
    const int g64 = tid >> 6;
    const int n   = tid & 63;
    for (int rep = 0; rep < 8; rep++) {
        int l = lc*32 + rep*4 + g64;
        vecs[g64][n] = heig[l*HD + h*64 + n];
        __syncthreads();
        float2 acc = make_float2(0.0f, 0.0f);
#pragma unroll 8
        for (int o = 0; o < 64; o++) {
            float2 m = Vs[n*65 + o], v = vecs[g64][o];
            acc.x += m.x*v.x - m.y*v.y;
            acc.y += m.x*v.y + m.y*v.x;
        }
        hr_out[(size_t)l*DIMN + h*128 + n*2]     = acc.x;
        hr_out[(size_t)l*DIMN + h*128 + n*2 + 1] = acc.y;
        if (l == LL-1) {
            if (out_size >= OUT_Y + 2*HD) {
                out[OUT_Y + (h*64+n)*2]     = acc.x;
                out[OUT_Y + (h*64+n)*2 + 1] = acc.y;
            } else if (out_size >= OUT_Y + HD) {
                out[OUT_Y + h*64 + n] = acc.x;
            }
        }
        __syncthreads();
    }
}

// ---------------- launch ---------------------------------------------------
extern "C" void kernel_launch(void* const* d_in, const int* in_sizes, int n_in,
                              void* d_out, int out_size)
{
    const float* x        = (const float*)d_in[0];
    const float* hreal    = (const float*)d_in[1];
    const float* himag    = (const float*)d_in[2];
    const float* w_in1    = (const float*)d_in[3];
    const float* b_in1    = (const float*)d_in[4];
    const float* w_in2    = (const float*)d_in[5];
    const float* b_in2    = (const float*)d_in[6];
    const float* w_out1   = (const float*)d_in[7];
    const float* b_out1   = (const float*)d_in[8];
    const float* w_out2   = (const float*)d_in[9];
    const float* b_out2   = (const float*)d_in[10];
    const float* mvr      = (const float*)d_in[11];
    const float* mvi      = (const float*)d_in[12];
    float* out = (float*)d_out;

    float *t1, *part, *hr, *y1;
    float2 *xc, *a, *vinv, *w, *heig, *sP, *sQ, *sIn;
    cudaGetSymbolAddress((void**)&t1,   g_t1);
    cudaGetSymbolAddress((void**)&part, g_part);
    cudaGetSymbolAddress((void**)&xc,   g_xc);
    cudaGetSymbolAddress((void**)&a,    g_a);
    cudaGetSymbolAddress((void**)&vinv, g_vinv);
    cudaGetSymbolAddress((void**)&w,    g_w);
    cudaGetSymbolAddress((void**)&heig, g_heig);
    cudaGetSymbolAddress((void**)&hr,   g_hr);
    cudaGetSymbolAddress((void**)&y1,   g_y1);
    cudaGetSymbolAddress((void**)&sP,   g_sP);
    cudaGetSymbolAddress((void**)&sQ,   g_sQ);
    cudaGetSymbolAddress((void**)&sIn,  g_sIn);

    cudaFuncSetAttribute(inv_kernel, cudaFuncAttributeMaxDynamicSharedMemorySize, 65536);

    const int MN1 = LL * DIMN;       // 262144

    // Vinv (independent)
    inv_kernel<<<HH, 512, 65536>>>(mvr, mvi, vinv);

    // t1 = silu(x @ w_in1 + b_in1)   split-K=8
    gemm_tc_sk<<<dim3(DIMN/128, LL/64, 8), 256>>>(x, w_in1, part, LL, DIMN, DIMN, 8);
    reduce_kernel<<<(MN1/4 + 255)/256, 256>>>(part, b_in1, t1, MN1, DIMN, 8, 1);

    // t2 partials = t1 @ w_in2 ; fused reduce -> xc, a   split-K=4
    gemm_tc_sk<<<dim3(2*DIMN/128, LL/64, 4), 256>>>(t1, w_in2, part, LL, 2*DIMN, DIMN, 4);
    reduce_prep_kernel<<<(LL*HD + 255)/256, 256>>>(part, b_in2, xc, a, 4);

    // w[0..256] = Vinv @ [hidden, xc[0..255]]
    matvec_vinv_t<<<dim3(9, HH), 256>>>(vinv, xc, hreal, himag, w);

    // chunked diagonal recurrence
    scanA_kernel<<<16, HD>>>(a, w, sP, sQ);
    scanB_kernel<<<1, HD>>>(sP, sQ, sIn);
    scanC_kernel<<<16, HD>>>(a, w, sIn, heig);

    // back to original basis; pack hr; write hidden_next
    matvec_v_t<<<dim3(8, HH), 256>>>(mvr, mvi, heig, hr, out, out_size);

    // y1 = silu(hr @ w_out1 + b_out1)   split-K=8
    gemm_tc_sk<<<dim3(DIMN/128, LL/64, 8), 256>>>(hr, w_out1, part, LL, DIMN, DIMN, 8);
    reduce_kernel<<<(MN1/4 + 255)/256, 256>>>(part, b_out1, y1, MN1, DIMN, 8, 1);

    // y = y1 @ w_out2 + b_out2 -> d_out   split-K=8
    gemm_tc_sk<<<dim3(DIMN/128, LL/64, 8), 256>>>(y1, w_out2, part, LL, DIMN, DIMN, 8);
    reduce_kernel<<<(MN1/4 + 255)/256, 256>>>(part, b_out2, out, MN1, DIMN, 8, 0);
}

// round 10
// speedup vs baseline: 4.4825x; 1.1560x over previous
#include <cuda_runtime.h>
#include <cuda_bf16.h>

// Shapes (fixed by the problem)
#define DIMN 1024
#define HH 8
#define DD 64
#define LL 256
#define HD 512           // H*D
#define OUT_Y (LL*DIMN)  // 262144

// ---------------- scratch (device globals; no allocation allowed) ----------
__device__ float  g_t1[LL*DIMN];
__device__ float  g_part[16*LL*DIMN];    // split-K partials (16MB)
__device__ float2 g_xc[LL*HD];
__device__ float2 g_a[LL*HD];
__device__ float2 g_vinv[HH*DD*DD];
__device__ float2 g_w[(LL+1)*HD];
__device__ float2 g_heig[LL*HD];
__device__ float  g_hr[LL*DIMN];
__device__ float  g_y1[LL*DIMN];
__device__ float2 g_sP[16*HD];
__device__ float2 g_sQ[16*HD];
__device__ float2 g_sIn[16*HD];

__device__ __forceinline__ float2 cmulf(float2 a, float2 b) {
    return make_float2(a.x*b.x - a.y*b.y, a.x*b.y + a.y*b.x);
}

// ---------------- bf16 split helpers ---------------------------------------
// pack2(v0,v1): bf16x2 word, v0 in lower half (element k), v1 upper (k+1)
__device__ __forceinline__ unsigned pack2(float v0, float v1) {
    unsigned r;
    asm("cvt.rn.bf16x2.f32 %0, %1, %2;" : "=r"(r) : "f"(v1), "f"(v0));
    return r;
}
// split (v0,v1) into bf16x2 hi word + bf16x2 residual word
__device__ __forceinline__ void splitw(float v0, float v1, unsigned& h, unsigned& l) {
    h = pack2(v0, v1);
    float h0 = __uint_as_float(h << 16);
    float h1 = __uint_as_float(h & 0xFFFF0000u);
    l = pack2(v0 - h0, v1 - h1);
}
__device__ __forceinline__ void mma_bf16(float* c, const unsigned* a, const unsigned* b) {
    asm volatile(
        "mma.sync.aligned.m16n8k16.row.col.f32.bf16.bf16.f32 "
        "{%0,%1,%2,%3}, {%4,%5,%6,%7}, {%8,%9}, {%0,%1,%2,%3};\n"
        : "+f"(c[0]), "+f"(c[1]), "+f"(c[2]), "+f"(c[3])
        : "r"(a[0]), "r"(a[1]), "r"(a[2]), "r"(a[3]), "r"(b[0]), "r"(b[1]));
}

// ---------------- split-K GEMM partials: P[z] = A[:,kz] @ W[kz,:] -----------
// Block tile 64x128, BK=32 elements (16 bf16x2 words), 256 threads = 8 warps
// (2 M x 4 N), warp tile 32x32, mma m16n8k16 bf16 with hi/lo compensation
// (3 MMA terms). Split done once at smem store; inner loop = LDS + MMA only.
#define APAD 20    // A row pitch in words (16 + 4)
#define BPAD 136   // B row pitch in words (128 + 8) -> conflict-free b-frags
__global__ __launch_bounds__(256) void gemm_bf_sk(
    const float* __restrict__ A, const float* __restrict__ W,
    float* __restrict__ P, int M, int N, int K, int ksplit)
{
    __shared__ unsigned Ah[64][APAD], Al[64][APAD];
    __shared__ unsigned Bh[16][BPAD], Bl[16][BPAD];

    const int tid  = threadIdx.x;
    const int lane = tid & 31;
    const int wid  = tid >> 5;
    const int wm   = wid & 1;      // 0..1 (M)
    const int wn   = wid >> 1;     // 0..3 (N)
    const int g    = lane >> 2;    // 0..7
    const int tig  = lane & 3;     // 0..3

    const int ksub = K / ksplit;
    const int k0g  = blockIdx.z * ksub;
    const int nc   = ksub >> 5;          // chunks of 32 K-elements

    float acc[2][4][4] = {};

    // A gmem: thread -> row ar, elements ak..ak+7 (two float4)
    const int ar = tid >> 2;             // 0..63
    const int ak = (tid & 3) << 3;       // 0,8,16,24
    const int aw = (tid & 3) << 2;       // word offset 0,4,8,12
    const float* Ap = A + (size_t)(blockIdx.y*64 + ar)*K + k0g + ak;

    // B gmem: two tasks per thread; task kw rows (2kw, 2kw+1), 4 cols
    const int kw0 = tid >> 5;            // 0..7
    const int kw1 = kw0 + 8;             // 8..15
    const int bn  = (tid & 31) << 2;     // 0..124
    const float* Wp = W + (size_t)k0g*N + blockIdx.x*128 + bn;

    float4 a0 = *(const float4*)Ap;
    float4 a1 = *(const float4*)(Ap + 4);
    float4 b00 = *(const float4*)(Wp + (size_t)(2*kw0)*N);
    float4 b01 = *(const float4*)(Wp + (size_t)(2*kw0+1)*N);
    float4 b10 = *(const float4*)(Wp + (size_t)(2*kw1)*N);
    float4 b11 = *(const float4*)(Wp + (size_t)(2*kw1+1)*N);

    for (int c = 0; c < nc; c++) {
        if (c) __syncthreads();
        {
            uint4 h4, l4;
            // A: words = consecutive element pairs along K
            splitw(a0.x, a0.y, h4.x, l4.x); splitw(a0.z, a0.w, h4.y, l4.y);
            splitw(a1.x, a1.y, h4.z, l4.z); splitw(a1.z, a1.w, h4.w, l4.w);
            *(uint4*)&Ah[ar][aw] = h4; *(uint4*)&Al[ar][aw] = l4;
            // B: word (kw, n) = (row 2kw, row 2kw+1) at column n
            splitw(b00.x, b01.x, h4.x, l4.x); splitw(b00.y, b01.y, h4.y, l4.y);
            splitw(b00.z, b01.z, h4.z, l4.z); splitw(b00.w, b01.w, h4.w, l4.w);
            *(uint4*)&Bh[kw0][bn] = h4; *(uint4*)&Bl[kw0][bn] = l4;
            splitw(b10.x, b11.x, h4.x, l4.x); splitw(b10.y, b11.y, h4.y, l4.y);
            splitw(b10.z, b11.z, h4.z, l4.z); splitw(b10.w, b11.w, h4.w, l4.w);
            *(uint4*)&Bh[kw1][bn] = h4; *(uint4*)&Bl[kw1][bn] = l4;
        }
        __syncthreads();
        if (c + 1 < nc) {
            a0  = *(const float4*)(Ap + (c+1)*32);
            a1  = *(const float4*)(Ap + (c+1)*32 + 4);
            b00 = *(const float4*)(Wp + (size_t)((c+1)*32 + 2*kw0)*N);
            b01 = *(const float4*)(Wp + (size_t)((c+1)*32 + 2*kw0+1)*N);
            b10 = *(const float4*)(Wp + (size_t)((c+1)*32 + 2*kw1)*N);
            b11 = *(const float4*)(Wp + (size_t)((c+1)*32 + 2*kw1+1)*N);
        }

        // ---- A fragments (hi + lo) ----
        unsigned ah[2][2][4], al_[2][2][4];
#pragma unroll
        for (int ma = 0; ma < 2; ma++)
#pragma unroll
            for (int ka = 0; ka < 2; ka++)
#pragma unroll
                for (int j = 0; j < 4; j++) {
                    int row = wm*32 + ma*16 + g + (j & 1)*8;
                    int col = ka*8 + tig + (j >> 1)*4;
                    ah[ma][ka][j]  = Ah[row][col];
                    al_[ma][ka][j] = Al[row][col];
                }

        // ---- per-na: load B frags, fire MMAs ----
#pragma unroll
        for (int na = 0; na < 4; na++) {
            unsigned bh[2][2], bl[2][2];
#pragma unroll
            for (int ka = 0; ka < 2; ka++)
#pragma unroll
                for (int j = 0; j < 2; j++) {
                    int r  = ka*8 + tig + j*4;
                    int cc = wn*32 + na*8 + g;
                    bh[ka][j] = Bh[r][cc];
                    bl[ka][j] = Bl[r][cc];
                }
#pragma unroll
            for (int ma = 0; ma < 2; ma++)
#pragma unroll
                for (int ka = 0; ka < 2; ka++) {
                    mma_bf16(acc[ma][na], al_[ma][ka], bh[ka]);
                    mma_bf16(acc[ma][na], ah[ma][ka],  bl[ka]);
                    mma_bf16(acc[ma][na], ah[ma][ka],  bh[ka]);
                }
        }
        if (c + 1 == nc) break;
    }

    float* Pz = P + (size_t)blockIdx.z * M * N;
#pragma unroll
    for (int ma = 0; ma < 2; ma++) {
#pragma unroll
        for (int na = 0; na < 4; na++) {
            int row = blockIdx.y*64 + wm*32 + ma*16 + g;
            int col = blockIdx.x*128 + wn*32 + na*8 + 2*tig;
            *(float2*)&Pz[(size_t)row*N + col]     = make_float2(acc[ma][na][0], acc[ma][na][1]);
            *(float2*)&Pz[(size_t)(row+8)*N + col] = make_float2(acc[ma][na][2], acc[ma][na][3]);
        }
    }
}

// ---------------- reduce split-K partials + bias (+silu) -------------------
__global__ void reduce_kernel(const float* __restrict__ P,
                              const float* __restrict__ bias,
                              float* __restrict__ C,
                              int MN, int N, int ksplit, int act)
{
    int e = (blockIdx.x*blockDim.x + threadIdx.x) * 4;
    if (e >= MN) return;
    float4 s = *(const float4*)(P + e);
    for (int z = 1; z < ksplit; z++) {
        float4 p = *(const float4*)(P + (size_t)z*MN + e);
        s.x += p.x; s.y += p.y; s.z += p.z; s.w += p.w;
    }
    int c = e % N;
    float4 b = *(const float4*)(bias + c);
    s.x += b.x; s.y += b.y; s.z += b.z; s.w += b.w;
    if (act) {
        s.x = s.x / (1.0f + expf(-s.x));
        s.y = s.y / (1.0f + expf(-s.y));
        s.z = s.z / (1.0f + expf(-s.z));
        s.w = s.w / (1.0f + expf(-s.w));
    }
    *(float4*)(C + e) = s;
}

// ---------------- reduce partials of GEMM2 and emit xc + normalized a ------
__global__ void reduce_prep_kernel(const float* __restrict__ P,
                                   const float* __restrict__ bias,
                                   float2* __restrict__ xc, float2* __restrict__ a,
                                   int ksplit)
{
    int e = blockIdx.x*blockDim.x + threadIdx.x;   // 0 .. LL*HD-1
    if (e >= LL*HD) return;
    const int MN = LL * 2 * DIMN;
    int off = e * 4;
    float4 s = *(const float4*)(P + off);
    for (int z = 1; z < ksplit; z++) {
        float4 p = *(const float4*)(P + (size_t)z*MN + off);
        s.x += p.x; s.y += p.y; s.z += p.z; s.w += p.w;
    }
    int c = off % (2*DIMN);
    float4 b = *(const float4*)(bias + c);
    float xr = s.x + b.x, xi = s.y + b.y, ar = s.z + b.z, ai = s.w + b.w;
    xc[e] = make_float2(xr, xi);
    float m2 = ar*ar + ai*ai;
    float f = (m2/(1.0f+m2)) * rsqrtf(m2);   // sigmoid(log m2) * rsqrt(m2)
    a[e] = make_float2(ar*f, ai*f);
}

// ---------------- complex 64x64 inverse (Gauss-Jordan, partial pivot) ------
__global__ __launch_bounds__(512) void inv_kernel(
    const float* __restrict__ vr, const float* __restrict__ vi,
    float2* __restrict__ vinv)
{
    extern __shared__ float2 sh[];
    float2* Am = sh;          // 64*64
    float2* Im = sh + 4096;   // 64*64
    __shared__ float2 fac[64];
    __shared__ float2 pivval;
    __shared__ int piv;
    int h = blockIdx.x;
    int t = threadIdx.x;   // 512 threads

    for (int i = t; i < 4096; i += 512) {
        int n = i >> 6, o = i & 63;
        Am[i] = make_float2(vr[h*4096 + i], vi[h*4096 + i]);
        Im[i] = make_float2(n == o ? 1.0f : 0.0f, 0.0f);
    }
    __syncthreads();

    for (int k = 0; k < 64; k++) {
        if (t < 32) {
            float best = -1.0f; int bp = k;
            for (int r = k + t; r < 64; r += 32) {
                float2 v = Am[r*64+k];
                float m = v.x*v.x + v.y*v.y;
                if (m > best) { best = m; bp = r; }
            }
#pragma unroll
            for (int o = 16; o; o >>= 1) {
                float ob = __shfl_down_sync(0xffffffffu, best, o);
                int  obp = __shfl_down_sync(0xffffffffu, bp,   o);
                if (ob > best) { best = ob; bp = obp; }
            }
            if (t == 0) { piv = bp; pivval = Am[bp*64+k]; }
        }
        __syncthreads();
        const int p = piv;
        const float2 pv = pivval;
        const float im2 = 1.0f/(pv.x*pv.x + pv.y*pv.y);
        const float2 pinv = make_float2(pv.x*im2, -pv.y*im2);

        if (t < 128) {
            float2* Mm = (t < 64) ? Am : Im;
            int c = t & 63;
            float2 rp = Mm[p*64+c];
            float2 rk = Mm[k*64+c];
            Mm[k*64+c] = cmulf(rp, pinv);
            if (p != k) Mm[p*64+c] = rk;
        }
        __syncthreads();
        if (t < 64) fac[t] = Am[t*64+k];
        __syncthreads();

        {
            int c = t & 63;
            float2* Mm = ((t >> 6) & 1) ? Im : Am;
            int rs = t >> 7;
            float2 pk = Mm[k*64+c];
#pragma unroll 4
            for (int r = rs; r < 64; r += 4) {
                if (r == k) continue;
                float2 f = fac[r];
                float2 v = Mm[r*64+c];
                v.x -= f.x*pk.x - f.y*pk.y;
                v.y -= f.x*pk.y + f.y*pk.x;
                Mm[r*64+c] = v;
            }
        }
        __syncthreads();
    }
    for (int i = t; i < 4096; i += 512) vinv[h*4096 + i] = Im[i];
}

// ---------------- tiled matvec: w[li] = Vinv[h] @ [hidden | xc[li-1]] ------
__global__ __launch_bounds__(256) void matvec_vinv_t(
    const float2* __restrict__ vinv, const float2* __restrict__ xc,
    const float* __restrict__ hreal, const float* __restrict__ himag,
    float2* __restrict__ w)
{
    __shared__ float2 Vs[64*65];
    __shared__ float2 vecs[4][64];
    const int lc = blockIdx.x;   // 0..8
    const int h  = blockIdx.y;
    const int tid = threadIdx.x;
    for (int i = tid; i < 4096; i += 256) {
        int n = i >> 6, o = i & 63;
        Vs[n*65 + o] = vinv[h*4096 + i];
    }
    __syncthreads();
    const int g64 = tid >> 6;    // 0..3
    const int n   = tid & 63;
    for (int rep = 0; rep < 8; rep++) {
        int li = lc*32 + rep*4 + g64;
        if (li <= LL) {
            if (li == 0) vecs[g64][n] = make_float2(hreal[h*64+n], himag[h*64+n]);
            else         vecs[g64][n] = xc[(li-1)*HD + h*64 + n];
        }
        __syncthreads();
        if (li <= LL) {
            float2 acc = make_float2(0.0f, 0.0f);
#pragma unroll 8
            for (int o = 0; o < 64; o++) {
                float2 m = Vs[n*65 + o], v = vecs[g64][o];
                acc.x += m.x*v.x - m.y*v.y;
                acc.y += m.x*v.y + m.y*v.x;
            }
            w[li*HD + h*64 + n] = acc;
        }
        __syncthreads();
    }
}

// ---------------- chunked scan: s[m] = a[m]*(s[m-1]+w[m]) ------------------
__global__ void scanA_kernel(const float2* __restrict__ a,
                             const float2* __restrict__ w,
                             float2* __restrict__ sP, float2* __restrict__ sQ)
{
    int c = blockIdx.x;      // 0..15
    int hd = threadIdx.x;    // 0..511
    float2 Pp = make_float2(1.0f, 0.0f);
    float2 S  = make_float2(0.0f, 0.0f);
#pragma unroll
    for (int i = 0; i < 16; i++) {
        int m = c*16 + i;
        float2 wm = w[m*HD + hd];
        float2 am = a[m*HD + hd];
        float2 t = make_float2(S.x + wm.x, S.y + wm.y);
        S  = cmulf(am, t);
        Pp = cmulf(am, Pp);
    }
    sP[c*HD + hd] = Pp;
    sQ[c*HD + hd] = S;
}
__global__ void scanB_kernel(const float2* __restrict__ sP,
                             const float2* __restrict__ sQ,
                             float2* __restrict__ sIn)
{
    int hd = threadIdx.x;
    float2 s = make_float2(0.0f, 0.0f);
#pragma unroll
    for (int c = 0; c < 16; c++) {
        sIn[c*HD + hd] = s;
        float2 p = sP[c*HD + hd];
        float2 q = sQ[c*HD + hd];
        float2 t = cmulf(p, s);
        s = make_float2(t.x + q.x, t.y + q.y);
    }
}
__global__ void scanC_kernel(const float2* __restrict__ a,
                             const float2* __restrict__ w,
                             const float2* __restrict__ sIn,
                             float2* __restrict__ heig)
{
    int c = blockIdx.x;
    int hd = threadIdx.x;
    float2 s = sIn[c*HD + hd];
#pragma unroll
    for (int i = 0; i < 16; i++) {
        int m = c*16 + i;
        float2 wm = w[m*HD + hd];
        float2 am = a[m*HD + hd];
        float2 t = make_float2(s.x + wm.x, s.y + wm.y);
        s = cmulf(am, t);
        float2 wn = w[(m+1)*HD + hd];
        heig[m*HD + hd] = make_float2(s.x + wn.x, s.y + wn.y);
    }
}

// ---------------- tiled matvec: out_h[l] = V[h] @ heig[l]; pack hr ---------
__global__ __launch_bounds__(256) void matvec_v_t(
    const float* __restrict__ vr, const float* __restrict__ vi,
    const float2* __restrict__ heig,
    float* __restrict__ hr_out, float* __restrict__ out, int out_size)
{
    __shared__ float2 Vs[64*65];
    __shared__ float2 vecs[4][64];
    const int lc = blockIdx.x;   // 0..7
    const int h  = blockIdx.y;
    const int tid = threadIdx.x;
    for (int i = tid; i < 4096; i += 256) {
        int n = i >> 6, o = i & 63;
        Vs[n*65 + o] = make_float2(vr[h*4096 + i], vi[h*4096 + i]);
    }
    __syncthreads();
    const int g64 = tid >> 6;
    const int n   = tid & 63;
    for (int rep = 0; rep < 8; rep++) {
        int l = lc*32 + rep*4 + g64;
        vecs[g64][n] = heig[l*HD + h*64 + n];
        __syncthreads();
        float2 acc = make_float2(0.0f, 0.0f);
#pragma unroll 8
        for (int o = 0; o < 64; o++) {
            float2 m = Vs[n*65 + o], v = vecs[g64][o];
            acc.x += m.x*v.x - m.y*v.y;
            acc.y += m.x*v.y + m.y*v.x;
        }
        hr_out[(size_t)l*DIMN + h*128 + n*2]     = acc.x;
        hr_out[(size_t)l*DIMN + h*128 + n*2 + 1] = acc.y;
        if (l == LL-1) {
            if (out_size >= OUT_Y + 2*HD) {
                out[OUT_Y + (h*64+n)*2]     = acc.x;
                out[OUT_Y + (h*64+n)*2 + 1] = acc.y;
            } else if (out_size >= OUT_Y + HD) {
                out[OUT_Y + h*64 + n] = acc.x;
            }
        }
        __syncthreads();
    }
}

// ---------------- launch ---------------------------------------------------
extern "C" void kernel_launch(void* const* d_in, const int* in_sizes, int n_in,
                              void* d_out, int out_size)
{
    const float* x        = (const float*)d_in[0];
    const float* hreal    = (const float*)d_in[1];
    const float* himag    = (const float*)d_in[2];
    const float* w_in1    = (const float*)d_in[3];
    const float* b_in1    = (const float*)d_in[4];
    const float* w_in2    = (const float*)d_in[5];
    const float* b_in2    = (const float*)d_in[6];
    const float* w_out1   = (const float*)d_in[7];
    const float* b_out1   = (const float*)d_in[8];
    const float* w_out2   = (const float*)d_in[9];
    const float* b_out2   = (const float*)d_in[10];
    const float* mvr      = (const float*)d_in[11];
    const float* mvi      = (const float*)d_in[12];
    float* out = (float*)d_out;

    float *t1, *part, *hr, *y1;
    float2 *xc, *a, *vinv, *w, *heig, *sP, *sQ, *sIn;
    cudaGetSymbolAddress((void**)&t1,   g_t1);
    cudaGetSymbolAddress((void**)&part, g_part);
    cudaGetSymbolAddress((void**)&xc,   g_xc);
    cudaGetSymbolAddress((void**)&a,    g_a);
    cudaGetSymbolAddress((void**)&vinv, g_vinv);
    cudaGetSymbolAddress((void**)&w,    g_w);
    cudaGetSymbolAddress((void**)&heig, g_heig);
    cudaGetSymbolAddress((void**)&hr,   g_hr);
    cudaGetSymbolAddress((void**)&y1,   g_y1);
    cudaGetSymbolAddress((void**)&sP,   g_sP);
    cudaGetSymbolAddress((void**)&sQ,   g_sQ);
    cudaGetSymbolAddress((void**)&sIn,  g_sIn);

    cudaFuncSetAttribute(inv_kernel, cudaFuncAttributeMaxDynamicSharedMemorySize, 65536);

    const int MN1 = LL * DIMN;       // 262144

    // Vinv (independent)
    inv_kernel<<<HH, 512, 65536>>>(mvr, mvi, vinv);

    // t1 = silu(x @ w_in1 + b_in1)   split-K=16 (512 CTAs)
    gemm_bf_sk<<<dim3(DIMN/128, LL/64, 16), 256>>>(x, w_in1, part, LL, DIMN, DIMN, 16);
    reduce_kernel<<<(MN1/4 + 255)/256, 256>>>(part, b_in1, t1, MN1, DIMN, 16, 1);

    // t2 partials = t1 @ w_in2 ; fused reduce -> xc, a   split-K=8 (512 CTAs)
    gemm_bf_sk<<<dim3(2*DIMN/128, LL/64, 8), 256>>>(t1, w_in2, part, LL, 2*DIMN, DIMN, 8);
    reduce_prep_kernel<<<(LL*HD + 255)/256, 256>>>(part, b_in2, xc, a, 8);

    // w[0..256] = Vinv @ [hidden, xc[0..255]]
    matvec_vinv_t<<<dim3(9, HH), 256>>>(vinv, xc, hreal, himag, w);

    // chunked diagonal recurrence
    scanA_kernel<<<16, HD>>>(a, w, sP, sQ);
    scanB_kernel<<<1, HD>>>(sP, sQ, sIn);
    scanC_kernel<<<16, HD>>>(a, w, sIn, heig);

    // back to original basis; pack hr; write hidden_next
    matvec_v_t<<<dim3(8, HH), 256>>>(mvr, mvi, heig, hr, out, out_size);

    // y1 = silu(hr @ w_out1 + b_out1)   split-K=16
    gemm_bf_sk<<<dim3(DIMN/128, LL/64, 16), 256>>>(hr, w_out1, part, LL, DIMN, DIMN, 16);
    reduce_kernel<<<(MN1/4 + 255)/256, 256>>>(part, b_out1, y1, MN1, DIMN, 16, 1);

    // y = y1 @ w_out2 + b_out2 -> d_out   split-K=16
    gemm_bf_sk<<<dim3(DIMN/128, LL/64, 16), 256>>>(y1, w_out2, part, LL, DIMN, DIMN, 16);
    reduce_kernel<<<(MN1/4 + 255)/256, 256>>>(part, b_out2, out, MN1, DIMN, 16, 0);
}